// round 1
// baseline (speedup 1.0000x reference)
#include <cuda_runtime.h>
#include <math.h>

#define NROWS   131072          // 64*2048
#define DIN     384
#define DHID    256
#define DLAT    128
#define KC      256
#define TM      32
#define NTHREADS 256

// shared memory layout (in floats):
//  [0,12288)    sX  (32x384)   -- aliased after GEMM1: sH (32x256) at [0,8192), sZ (32x128) at [8192,12288)
//  [12288,20736) sW  (8448)    -- W1/W2 k-tiles and transposed codebook tiles (32 x 264 padded)
//  [20736,20992) sCn (256)     -- codebook squared norms
//  [20992,21008) sLoss (8 doubles)
#define SMEM_FLOATS 21008
#define SMEM_BYTES  (SMEM_FLOATS * 4)

__device__ double g_loss_accum;

__device__ __forceinline__ float warp_sum(float v) {
#pragma unroll
    for (int o = 16; o > 0; o >>= 1) v += __shfl_xor_sync(0xffffffffu, v, o);
    return v;
}

__global__ void vq_zero_kernel() { g_loss_accum = 0.0; }

__global__ void vq_finalize_kernel(float* out_loss) {
    out_loss[0] = (float)(1.25 * g_loss_accum / (double)((long long)NROWS * DLAT));
}

extern "C" __global__ void __launch_bounds__(NTHREADS, 2)
vq_fused_kernel(const float* __restrict__ emb,
                const float* __restrict__ W1, const float* __restrict__ b1,
                const float* __restrict__ g1, const float* __restrict__ be1,
                const float* __restrict__ W2, const float* __restrict__ b2,
                const float* __restrict__ g2, const float* __restrict__ be2,
                const float* __restrict__ cb,
                float* __restrict__ outZ,
                float* __restrict__ outIdx,
                int writeAux)
{
    extern __shared__ float sm[];
    float*  sX   = sm;                       // 32x384
    float*  sH   = sm;                       // 32x256 (aliases sX after GEMM1)
    float*  sZ   = sm + 8192;                // 32x128
    float*  sW   = sm + 12288;               // tiles
    float*  sCn  = sm + 20736;               // 256
    double* sLoss = (double*)(sm + 20992);   // 8 doubles

    const int tid  = threadIdx.x;
    const int wid  = tid >> 5;
    const int lane = tid & 31;
    const int rb   = wid * 4;                // this warp's 4 rows within the 32-row tile
    const int r0   = blockIdx.x * TM;
    const int c8   = lane * 8;               // 8-col group (GEMM1 / dist)
    const int c4   = lane * 4;               // 4-col group (GEMM2)

    // ---- stage X tile (coalesced float4) ----
    {
        const float4* e4 = (const float4*)emb + (size_t)r0 * (DIN / 4);
        float4* x4 = (float4*)sX;
#pragma unroll
        for (int i = 0; i < 12; i++) x4[tid + i * 256] = e4[tid + i * 256];
    }
    // ---- codebook squared norms (one code per thread) ----
    {
        const float4* cv4 = (const float4*)cb + (size_t)tid * (DLAT / 4);
        float s = 0.f;
#pragma unroll
        for (int q = 0; q < 32; q++) {
            float4 v = cv4[q];
            s += v.x * v.x + v.y * v.y + v.z * v.z + v.w * v.w;
        }
        sCn[tid] = s;
    }

    // =================== GEMM1: [32,384] @ W1[384,256] ===================
    float acc[4][8];
#pragma unroll
    for (int i = 0; i < 4; i++)
#pragma unroll
        for (int j = 0; j < 8; j++) acc[i][j] = 0.f;

    for (int kt = 0; kt < DIN; kt += 32) {
        __syncthreads();
        {
            const float4* w4 = (const float4*)W1 + kt * 64;
            float4* t4 = (float4*)sW;
#pragma unroll
            for (int i = 0; i < 8; i++) t4[tid + i * 256] = w4[tid + i * 256];
        }
        __syncthreads();
#pragma unroll 8
        for (int kk = 0; kk < 32; kk++) {
            float4 wa = ((float4*)sW)[kk * 64 + lane * 2];
            float4 wb = ((float4*)sW)[kk * 64 + lane * 2 + 1];
#pragma unroll
            for (int i = 0; i < 4; i++) {
                float x = sX[(rb + i) * 384 + kt + kk];
                acc[i][0] = fmaf(x, wa.x, acc[i][0]);
                acc[i][1] = fmaf(x, wa.y, acc[i][1]);
                acc[i][2] = fmaf(x, wa.z, acc[i][2]);
                acc[i][3] = fmaf(x, wa.w, acc[i][3]);
                acc[i][4] = fmaf(x, wb.x, acc[i][4]);
                acc[i][5] = fmaf(x, wb.y, acc[i][5]);
                acc[i][6] = fmaf(x, wb.z, acc[i][6]);
                acc[i][7] = fmaf(x, wb.w, acc[i][7]);
            }
        }
    }
    __syncthreads();   // all reads of sX/sW done before sH overwrites sX

    // =================== bias + LayerNorm1 + exact GELU ===================
    {
        float b1v[8], g1v[8], e1v[8];
        {
            float4 a = ((const float4*)(b1 + c8))[0], b = ((const float4*)(b1 + c8))[1];
            b1v[0]=a.x;b1v[1]=a.y;b1v[2]=a.z;b1v[3]=a.w;b1v[4]=b.x;b1v[5]=b.y;b1v[6]=b.z;b1v[7]=b.w;
            a = ((const float4*)(g1 + c8))[0]; b = ((const float4*)(g1 + c8))[1];
            g1v[0]=a.x;g1v[1]=a.y;g1v[2]=a.z;g1v[3]=a.w;g1v[4]=b.x;g1v[5]=b.y;g1v[6]=b.z;g1v[7]=b.w;
            a = ((const float4*)(be1 + c8))[0]; b = ((const float4*)(be1 + c8))[1];
            e1v[0]=a.x;e1v[1]=a.y;e1v[2]=a.z;e1v[3]=a.w;e1v[4]=b.x;e1v[5]=b.y;e1v[6]=b.z;e1v[7]=b.w;
        }
#pragma unroll
        for (int i = 0; i < 4; i++) {
            float v[8], s = 0.f;
#pragma unroll
            for (int j = 0; j < 8; j++) { v[j] = acc[i][j] + b1v[j]; s += v[j]; }
            s = warp_sum(s);
            float mean = s * (1.f / 256.f);
            float ss = 0.f;
#pragma unroll
            for (int j = 0; j < 8; j++) { float d = v[j] - mean; ss += d * d; }
            ss = warp_sum(ss);
            float rstd = rsqrtf(ss * (1.f / 256.f) + 1e-5f);
#pragma unroll
            for (int j = 0; j < 8; j++) {
                float t = (v[j] - mean) * rstd * g1v[j] + e1v[j];
                float h = 0.5f * t * (1.f + erff(t * 0.70710678118654752f));
                sH[(rb + i) * 256 + c8 + j] = h;
            }
        }
    }
    __syncthreads();

    // =================== GEMM2: [32,256] @ W2[256,128] ===================
    float acc2[4][4];
#pragma unroll
    for (int i = 0; i < 4; i++)
#pragma unroll
        for (int j = 0; j < 4; j++) acc2[i][j] = 0.f;

    for (int kt = 0; kt < DHID; kt += 32) {
        __syncthreads();
        {
            const float4* w4 = (const float4*)W2 + kt * 32;
            float4* t4 = (float4*)sW;
#pragma unroll
            for (int i = 0; i < 4; i++) t4[tid + i * 256] = w4[tid + i * 256];
        }
        __syncthreads();
#pragma unroll 8
        for (int kk = 0; kk < 32; kk++) {
            float4 wv = ((float4*)sW)[kk * 32 + lane];
#pragma unroll
            for (int i = 0; i < 4; i++) {
                float x = sH[(rb + i) * 256 + kt + kk];
                acc2[i][0] = fmaf(x, wv.x, acc2[i][0]);
                acc2[i][1] = fmaf(x, wv.y, acc2[i][1]);
                acc2[i][2] = fmaf(x, wv.z, acc2[i][2]);
                acc2[i][3] = fmaf(x, wv.w, acc2[i][3]);
            }
        }
    }
    __syncthreads();

    // =================== bias + LayerNorm2 -> z, ||z||^2 ===================
    float zsq[4];
    {
        float4 b2v = *((const float4*)(b2 + c4));
        float4 g2v = *((const float4*)(g2 + c4));
        float4 e2v = *((const float4*)(be2 + c4));
#pragma unroll
        for (int i = 0; i < 4; i++) {
            float v0 = acc2[i][0] + b2v.x, v1 = acc2[i][1] + b2v.y;
            float v2 = acc2[i][2] + b2v.z, v3 = acc2[i][3] + b2v.w;
            float s = warp_sum(v0 + v1 + v2 + v3);
            float mean = s * (1.f / 128.f);
            float d0 = v0 - mean, d1 = v1 - mean, d2 = v2 - mean, d3 = v3 - mean;
            float ss = warp_sum(d0 * d0 + d1 * d1 + d2 * d2 + d3 * d3);
            float rstd = rsqrtf(ss * (1.f / 128.f) + 1e-5f);
            float z0 = d0 * rstd * g2v.x + e2v.x;
            float z1 = d1 * rstd * g2v.y + e2v.y;
            float z2 = d2 * rstd * g2v.z + e2v.z;
            float z3 = d3 * rstd * g2v.w + e2v.w;
            zsq[i] = warp_sum(z0 * z0 + z1 * z1 + z2 * z2 + z3 * z3);
            float* zr = sZ + (rb + i) * 128 + c4;
            zr[0] = z0; zr[1] = z1; zr[2] = z2; zr[3] = z3;
        }
    }
    __syncthreads();

    // =================== distance GEMM: z[32,128] . cb[256,128]^T ===================
    float acc3[4][8];
#pragma unroll
    for (int i = 0; i < 4; i++)
#pragma unroll
        for (int j = 0; j < 8; j++) acc3[i][j] = 0.f;

    for (int kt = 0; kt < DLAT; kt += 32) {
        __syncthreads();
        // stage transposed codebook tile: sW[kk*264 + j] = cb[j][kt+kk]
        {
            const float4* cv4 = (const float4*)cb + (size_t)tid * 32 + (kt >> 2);
#pragma unroll
            for (int q = 0; q < 8; q++) {
                float4 v = cv4[q];
                int kk = q * 4;
                sW[(kk + 0) * 264 + tid] = v.x;
                sW[(kk + 1) * 264 + tid] = v.y;
                sW[(kk + 2) * 264 + tid] = v.z;
                sW[(kk + 3) * 264 + tid] = v.w;
            }
        }
        __syncthreads();
#pragma unroll 8
        for (int kk = 0; kk < 32; kk++) {
            float4 ca = ((float4*)sW)[kk * 66 + lane * 2];
            float4 cbv = ((float4*)sW)[kk * 66 + lane * 2 + 1];
#pragma unroll
            for (int i = 0; i < 4; i++) {
                float z = sZ[(rb + i) * 128 + kt + kk];
                acc3[i][0] = fmaf(z, ca.x,  acc3[i][0]);
                acc3[i][1] = fmaf(z, ca.y,  acc3[i][1]);
                acc3[i][2] = fmaf(z, ca.z,  acc3[i][2]);
                acc3[i][3] = fmaf(z, ca.w,  acc3[i][3]);
                acc3[i][4] = fmaf(z, cbv.x, acc3[i][4]);
                acc3[i][5] = fmaf(z, cbv.y, acc3[i][5]);
                acc3[i][6] = fmaf(z, cbv.z, acc3[i][6]);
                acc3[i][7] = fmaf(z, cbv.w, acc3[i][7]);
            }
        }
    }

    // =================== argmin + outputs + loss ===================
    double lsum = 0.0;
#pragma unroll
    for (int i = 0; i < 4; i++) {
        float best = INFINITY;
        int   bidx = 0;
#pragma unroll
        for (int j = 0; j < 8; j++) {
            // mimic reference rounding: (||z||^2 + ||c||^2) - 2*dot, fp32
            float d = (zsq[i] + sCn[c8 + j]) - 2.0f * acc3[i][j];
            if (d < best) { best = d; bidx = c8 + j; }
        }
#pragma unroll
        for (int o = 16; o > 0; o >>= 1) {
            float ob = __shfl_xor_sync(0xffffffffu, best, o);
            int   oi = __shfl_xor_sync(0xffffffffu, bidx, o);
            if (ob < best || (ob == best && oi < bidx)) { best = ob; bidx = oi; }
        }
        int r = r0 + rb + i;
        if (lane == 0 && writeAux) outIdx[r] = (float)bidx;
        float4 cv = ((const float4*)cb)[bidx * 32 + lane];
        ((float4*)outZ)[(size_t)r * 32 + lane] = cv;
        float4 zv = ((float4*)sZ)[(rb + i) * 32 + lane];
        float d0 = cv.x - zv.x, d1 = cv.y - zv.y, d2 = cv.z - zv.z, d3 = cv.w - zv.w;
        lsum += (double)(d0 * d0 + d1 * d1 + d2 * d2 + d3 * d3);
    }

#pragma unroll
    for (int o = 16; o > 0; o >>= 1) lsum += __shfl_down_sync(0xffffffffu, lsum, o);
    if (lane == 0) sLoss[wid] = lsum;
    __syncthreads();
    if (tid == 0 && writeAux) {
        double t = 0.0;
#pragma unroll
        for (int w = 0; w < 8; w++) t += sLoss[w];
        atomicAdd(&g_loss_accum, t);
    }
}

extern "C" void kernel_launch(void* const* d_in, const int* in_sizes, int n_in,
                              void* d_out, int out_size)
{
    const float* emb = (const float*)d_in[0];
    const float* W1  = (const float*)d_in[1];
    const float* b1  = (const float*)d_in[2];
    const float* g1  = (const float*)d_in[3];
    const float* be1 = (const float*)d_in[4];
    const float* W2  = (const float*)d_in[5];
    const float* b2  = (const float*)d_in[6];
    const float* g2  = (const float*)d_in[7];
    const float* be2 = (const float*)d_in[8];
    const float* cb  = (const float*)d_in[9];

    float* out     = (float*)d_out;
    float* outZ    = out;
    float* outLoss = out + (size_t)NROWS * DLAT;     // after 16777216 z_q floats
    float* outIdx  = outLoss + 1;                     // then 131072 indices (as float)
    int writeAux = (out_size >= NROWS * DLAT + 1 + NROWS) ? 1 : 0;

    cudaFuncSetAttribute(vq_fused_kernel,
                         cudaFuncAttributeMaxDynamicSharedMemorySize, SMEM_BYTES);

    vq_zero_kernel<<<1, 1>>>();
    vq_fused_kernel<<<NROWS / TM, NTHREADS, SMEM_BYTES>>>(
        emb, W1, b1, g1, be1, W2, b2, g2, be2, cb, outZ, outIdx, writeAux);
    if (writeAux) vq_finalize_kernel<<<1, 1>>>(outLoss);
}

// round 2
// speedup vs baseline: 1.0532x; 1.0532x over previous
#include <cuda_runtime.h>
#include <math.h>

#define NROWS   131072          // 64*2048
#define DIN     384
#define DHID    256
#define DLAT    128
#define KC      256
#define TM      32
#define NTHREADS 256
#define NBLOCKS (NROWS / TM)    // 4096

// shared memory layout (in floats):
//  [0,12288)    sX  (32x384)   -- aliased after GEMM1: sH (32x256) at [0,8192), sZ (32x128) at [8192,12288)
//  [12288,20736) sW  (8448)    -- W1/W2 k-tiles and transposed codebook tiles (32 x 264 padded)
//  [20736,20992) sCn (256)     -- codebook squared norms
//  [20992,21008) sLoss (8 doubles)
#define SMEM_FLOATS 21008
#define SMEM_BYTES  (SMEM_FLOATS * 4)

__device__ double       g_partials[NBLOCKS];
__device__ unsigned int g_ticket = 0;

typedef unsigned long long u64;

__device__ __forceinline__ float warp_sum(float v) {
#pragma unroll
    for (int o = 16; o > 0; o >>= 1) v += __shfl_xor_sync(0xffffffffu, v, o);
    return v;
}

// duplicate a float into both lanes of an f32x2 register pair
__device__ __forceinline__ u64 dup2(float x) {
    u64 r; asm("mov.b64 %0, {%1, %1};" : "=l"(r) : "f"(x)); return r;
}
// packed dual-FMA: d.lo = a.lo*b.lo + c.lo ; d.hi = a.hi*b.hi + c.hi
__device__ __forceinline__ u64 fma2(u64 a, u64 b, u64 c) {
    u64 d; asm("fma.rn.f32x2 %0, %1, %2, %3;" : "=l"(d) : "l"(a), "l"(b), "l"(c)); return d;
}
__device__ __forceinline__ void unpack2(u64 p, float& lo, float& hi) {
    asm("mov.b64 {%0, %1}, %2;" : "=f"(lo), "=f"(hi) : "l"(p));
}

extern "C" __global__ void __launch_bounds__(NTHREADS, 2)
vq_fused_kernel(const float* __restrict__ emb,
                const float* __restrict__ W1, const float* __restrict__ b1,
                const float* __restrict__ g1, const float* __restrict__ be1,
                const float* __restrict__ W2, const float* __restrict__ b2,
                const float* __restrict__ g2, const float* __restrict__ be2,
                const float* __restrict__ cb,
                float* __restrict__ outZ,
                float* __restrict__ outIdx,
                float* __restrict__ outLoss,
                int writeAux)
{
    extern __shared__ float sm[];
    float*  sX   = sm;                       // 32x384
    float*  sH   = sm;                       // 32x256 (aliases sX after GEMM1)
    float*  sZ   = sm + 8192;                // 32x128
    float*  sW   = sm + 12288;               // tiles
    float*  sCn  = sm + 20736;               // 256
    double* sLoss = (double*)(sm + 20992);   // 8 doubles

    const int tid  = threadIdx.x;
    const int wid  = tid >> 5;
    const int lane = tid & 31;
    const int rb   = wid * 4;                // this warp's 4 rows within the 32-row tile
    const int r0   = blockIdx.x * TM;
    const int c8   = lane * 8;               // 8-col group (GEMM1 / dist)
    const int c4   = lane * 4;               // 4-col group (GEMM2)

    // ---- stage X tile (coalesced float4) ----
    {
        const float4* e4 = (const float4*)emb + (size_t)r0 * (DIN / 4);
        float4* x4 = (float4*)sX;
#pragma unroll
        for (int i = 0; i < 12; i++) x4[tid + i * 256] = e4[tid + i * 256];
    }
    // ---- codebook squared norms (one code per thread) ----
    {
        const float4* cv4 = (const float4*)cb + (size_t)tid * (DLAT / 4);
        float s = 0.f;
#pragma unroll
        for (int q = 0; q < 32; q++) {
            float4 v = cv4[q];
            s += v.x * v.x + v.y * v.y + v.z * v.z + v.w * v.w;
        }
        sCn[tid] = s;
    }

    // =================== GEMM1: [32,384] @ W1[384,256]  (f32x2 packed) ===================
    // acc1[i][p] holds columns (c8+2p, c8+2p+1); per-column k-order identical to scalar.
    u64 acc1[4][4];
#pragma unroll
    for (int i = 0; i < 4; i++)
#pragma unroll
        for (int p = 0; p < 4; p++) acc1[i][p] = 0ULL;

    for (int kt = 0; kt < DIN; kt += 32) {
        __syncthreads();
        {
            const float4* w4 = (const float4*)W1 + kt * 64;
            float4* t4 = (float4*)sW;
#pragma unroll
            for (int i = 0; i < 8; i++) t4[tid + i * 256] = w4[tid + i * 256];
        }
        __syncthreads();
#pragma unroll 8
        for (int kk = 0; kk < 32; kk++) {
            // 16B loads give two naturally-paired f32x2 operands each
            ulonglong2 wA = ((const ulonglong2*)sW)[kk * 64 + lane * 2];
            ulonglong2 wB = ((const ulonglong2*)sW)[kk * 64 + lane * 2 + 1];
#pragma unroll
            for (int i = 0; i < 4; i++) {
                u64 xx = dup2(sX[(rb + i) * 384 + kt + kk]);
                acc1[i][0] = fma2(xx, wA.x, acc1[i][0]);
                acc1[i][1] = fma2(xx, wA.y, acc1[i][1]);
                acc1[i][2] = fma2(xx, wB.x, acc1[i][2]);
                acc1[i][3] = fma2(xx, wB.y, acc1[i][3]);
            }
        }
    }
    __syncthreads();   // all reads of sX/sW done before sH overwrites sX

    // =================== bias + LayerNorm1 + exact GELU ===================
    {
        float b1v[8], g1v[8], e1v[8];
        {
            float4 a = ((const float4*)(b1 + c8))[0], b = ((const float4*)(b1 + c8))[1];
            b1v[0]=a.x;b1v[1]=a.y;b1v[2]=a.z;b1v[3]=a.w;b1v[4]=b.x;b1v[5]=b.y;b1v[6]=b.z;b1v[7]=b.w;
            a = ((const float4*)(g1 + c8))[0]; b = ((const float4*)(g1 + c8))[1];
            g1v[0]=a.x;g1v[1]=a.y;g1v[2]=a.z;g1v[3]=a.w;g1v[4]=b.x;g1v[5]=b.y;g1v[6]=b.z;g1v[7]=b.w;
            a = ((const float4*)(be1 + c8))[0]; b = ((const float4*)(be1 + c8))[1];
            e1v[0]=a.x;e1v[1]=a.y;e1v[2]=a.z;e1v[3]=a.w;e1v[4]=b.x;e1v[5]=b.y;e1v[6]=b.z;e1v[7]=b.w;
        }
#pragma unroll
        for (int i = 0; i < 4; i++) {
            float v[8], s = 0.f;
#pragma unroll
            for (int p = 0; p < 4; p++) unpack2(acc1[i][p], v[2*p], v[2*p+1]);
#pragma unroll
            for (int j = 0; j < 8; j++) { v[j] = v[j] + b1v[j]; s += v[j]; }
            s = warp_sum(s);
            float mean = s * (1.f / 256.f);
            float ss = 0.f;
#pragma unroll
            for (int j = 0; j < 8; j++) { float d = v[j] - mean; ss += d * d; }
            ss = warp_sum(ss);
            float rstd = rsqrtf(ss * (1.f / 256.f) + 1e-5f);
#pragma unroll
            for (int j = 0; j < 8; j++) {
                float t = (v[j] - mean) * rstd * g1v[j] + e1v[j];
                float h = 0.5f * t * (1.f + erff(t * 0.70710678118654752f));
                sH[(rb + i) * 256 + c8 + j] = h;
            }
        }
    }
    __syncthreads();

    // =================== GEMM2: [32,256] @ W2[256,128]  (f32x2 packed) ===================
    u64 acc2[4][2];
#pragma unroll
    for (int i = 0; i < 4; i++) { acc2[i][0] = 0ULL; acc2[i][1] = 0ULL; }

    for (int kt = 0; kt < DHID; kt += 32) {
        __syncthreads();
        {
            const float4* w4 = (const float4*)W2 + kt * 32;
            float4* t4 = (float4*)sW;
#pragma unroll
            for (int i = 0; i < 4; i++) t4[tid + i * 256] = w4[tid + i * 256];
        }
        __syncthreads();
#pragma unroll 8
        for (int kk = 0; kk < 32; kk++) {
            ulonglong2 wv = ((const ulonglong2*)sW)[kk * 32 + lane];
#pragma unroll
            for (int i = 0; i < 4; i++) {
                u64 xx = dup2(sH[(rb + i) * 256 + kt + kk]);
                acc2[i][0] = fma2(xx, wv.x, acc2[i][0]);
                acc2[i][1] = fma2(xx, wv.y, acc2[i][1]);
            }
        }
    }
    __syncthreads();

    // =================== bias + LayerNorm2 -> z, ||z||^2 ===================
    float zsq[4];
    {
        float4 b2v = *((const float4*)(b2 + c4));
        float4 g2v = *((const float4*)(g2 + c4));
        float4 e2v = *((const float4*)(be2 + c4));
#pragma unroll
        for (int i = 0; i < 4; i++) {
            float a0, a1, a2, a3;
            unpack2(acc2[i][0], a0, a1);
            unpack2(acc2[i][1], a2, a3);
            float v0 = a0 + b2v.x, v1 = a1 + b2v.y;
            float v2 = a2 + b2v.z, v3 = a3 + b2v.w;
            float s = warp_sum(v0 + v1 + v2 + v3);
            float mean = s * (1.f / 128.f);
            float d0 = v0 - mean, d1 = v1 - mean, d2 = v2 - mean, d3 = v3 - mean;
            float ss = warp_sum(d0 * d0 + d1 * d1 + d2 * d2 + d3 * d3);
            float rstd = rsqrtf(ss * (1.f / 128.f) + 1e-5f);
            float z0 = d0 * rstd * g2v.x + e2v.x;
            float z1 = d1 * rstd * g2v.y + e2v.y;
            float z2 = d2 * rstd * g2v.z + e2v.z;
            float z3 = d3 * rstd * g2v.w + e2v.w;
            zsq[i] = warp_sum(z0 * z0 + z1 * z1 + z2 * z2 + z3 * z3);
            float* zr = sZ + (rb + i) * 128 + c4;
            zr[0] = z0; zr[1] = z1; zr[2] = z2; zr[3] = z3;
        }
    }
    __syncthreads();

    // =================== distance GEMM: z[32,128] . cb[256,128]^T  (f32x2 packed) ===================
    u64 acc3[4][4];
#pragma unroll
    for (int i = 0; i < 4; i++)
#pragma unroll
        for (int p = 0; p < 4; p++) acc3[i][p] = 0ULL;

    for (int kt = 0; kt < DLAT; kt += 32) {
        __syncthreads();
        // stage transposed codebook tile: sW[kk*264 + j] = cb[j][kt+kk]
        {
            const float4* cv4 = (const float4*)cb + (size_t)tid * 32 + (kt >> 2);
#pragma unroll
            for (int q = 0; q < 8; q++) {
                float4 v = cv4[q];
                int kk = q * 4;
                sW[(kk + 0) * 264 + tid] = v.x;
                sW[(kk + 1) * 264 + tid] = v.y;
                sW[(kk + 2) * 264 + tid] = v.z;
                sW[(kk + 3) * 264 + tid] = v.w;
            }
        }
        __syncthreads();
#pragma unroll 8
        for (int kk = 0; kk < 32; kk++) {
            ulonglong2 cA = ((const ulonglong2*)sW)[kk * 66 + lane * 2];
            ulonglong2 cB = ((const ulonglong2*)sW)[kk * 66 + lane * 2 + 1];
#pragma unroll
            for (int i = 0; i < 4; i++) {
                u64 zz = dup2(sZ[(rb + i) * 128 + kt + kk]);
                acc3[i][0] = fma2(zz, cA.x, acc3[i][0]);
                acc3[i][1] = fma2(zz, cA.y, acc3[i][1]);
                acc3[i][2] = fma2(zz, cB.x, acc3[i][2]);
                acc3[i][3] = fma2(zz, cB.y, acc3[i][3]);
            }
        }
    }

    // =================== argmin + outputs + loss ===================
    double lsum = 0.0;
#pragma unroll
    for (int i = 0; i < 4; i++) {
        float dot[8];
#pragma unroll
        for (int p = 0; p < 4; p++) unpack2(acc3[i][p], dot[2*p], dot[2*p+1]);
        float best = INFINITY;
        int   bidx = 0;
#pragma unroll
        for (int j = 0; j < 8; j++) {
            // mimic reference rounding: (||z||^2 + ||c||^2) - 2*dot, fp32
            float d = (zsq[i] + sCn[c8 + j]) - 2.0f * dot[j];
            if (d < best) { best = d; bidx = c8 + j; }
        }
#pragma unroll
        for (int o = 16; o > 0; o >>= 1) {
            float ob = __shfl_xor_sync(0xffffffffu, best, o);
            int   oi = __shfl_xor_sync(0xffffffffu, bidx, o);
            if (ob < best || (ob == best && oi < bidx)) { best = ob; bidx = oi; }
        }
        int r = r0 + rb + i;
        if (lane == 0 && writeAux) outIdx[r] = (float)bidx;
        float4 cv = ((const float4*)cb)[bidx * 32 + lane];
        ((float4*)outZ)[(size_t)r * 32 + lane] = cv;
        float4 zv = ((float4*)sZ)[(rb + i) * 32 + lane];
        float d0 = cv.x - zv.x, d1 = cv.y - zv.y, d2 = cv.z - zv.z, d3 = cv.w - zv.w;
        lsum += (double)(d0 * d0 + d1 * d1 + d2 * d2 + d3 * d3);
    }

#pragma unroll
    for (int o = 16; o > 0; o >>= 1) lsum += __shfl_down_sync(0xffffffffu, lsum, o);
    if (lane == 0) sLoss[wid] = lsum;
    __syncthreads();

    // ---- per-block partial + last-block finalize (single-kernel loss) ----
    if (!writeAux) return;
    __shared__ unsigned int sIsLast;
    if (tid == 0) {
        double t = 0.0;
#pragma unroll
        for (int w = 0; w < 8; w++) t += sLoss[w];
        g_partials[blockIdx.x] = t;
        __threadfence();
        unsigned int old = atomicAdd(&g_ticket, 1u);
        sIsLast = (old == (unsigned int)(gridDim.x - 1)) ? 1u : 0u;
    }
    __syncthreads();
    if (sIsLast) {
        __threadfence();
        double s = 0.0;
#pragma unroll
        for (int q = 0; q < NBLOCKS / NTHREADS; q++)
            s += g_partials[tid * (NBLOCKS / NTHREADS) + q];
#pragma unroll
        for (int o = 16; o > 0; o >>= 1) s += __shfl_down_sync(0xffffffffu, s, o);
        if (lane == 0) sLoss[wid] = s;
        __syncthreads();
        if (tid == 0) {
            double t = 0.0;
#pragma unroll
            for (int w = 0; w < 8; w++) t += sLoss[w];
            outLoss[0] = (float)(1.25 * t / (double)((long long)NROWS * DLAT));
            g_ticket = 0;   // reset for next (graph-replayed) launch
        }
    }
}

extern "C" void kernel_launch(void* const* d_in, const int* in_sizes, int n_in,
                              void* d_out, int out_size)
{
    const float* emb = (const float*)d_in[0];
    const float* W1  = (const float*)d_in[1];
    const float* b1  = (const float*)d_in[2];
    const float* g1  = (const float*)d_in[3];
    const float* be1 = (const float*)d_in[4];
    const float* W2  = (const float*)d_in[5];
    const float* b2  = (const float*)d_in[6];
    const float* g2  = (const float*)d_in[7];
    const float* be2 = (const float*)d_in[8];
    const float* cb  = (const float*)d_in[9];

    float* out     = (float*)d_out;
    float* outZ    = out;
    float* outLoss = out + (size_t)NROWS * DLAT;     // after 16777216 z_q floats
    float* outIdx  = outLoss + 1;                     // then 131072 indices (as float)
    int writeAux = (out_size >= NROWS * DLAT + 1 + NROWS) ? 1 : 0;

    cudaFuncSetAttribute(vq_fused_kernel,
                         cudaFuncAttributeMaxDynamicSharedMemorySize, SMEM_BYTES);

    vq_fused_kernel<<<NBLOCKS, NTHREADS, SMEM_BYTES>>>(
        emb, W1, b1, g1, be1, W2, b2, g2, be2, cb, outZ, outIdx, outLoss, writeAux);
}

// round 3
// speedup vs baseline: 1.6148x; 1.5332x over previous
#include <cuda_runtime.h>
#include <math.h>

#define NROWS   131072          // 64*2048
#define DIN     384
#define DHID    256
#define DLAT    128
#define KC      256
#define TM      64
#define NTHREADS 256
#define NBLOCKS (NROWS / TM)    // 2048

// shared memory layout (in floats):
//  [0,24576)     sX  (64x384)  -- aliased after GEMM1: sH (64x256) at [0,16384), sZ (64x128) at [16384,24576)
//  [24576,33024) sW  (8448)    -- W1/W2 k-tiles and transposed codebook tiles (32 x 264 padded)
//  [33024,33280) sCn (256)
//  [33280,33312) sLoss (8 doubles + pad)
#define SMEM_FLOATS 33312
#define SMEM_BYTES  (SMEM_FLOATS * 4)

__device__ double       g_partials[NBLOCKS];
__device__ unsigned int g_ticket = 0;

typedef unsigned long long u64;

__device__ __forceinline__ float warp_sum(float v) {
#pragma unroll
    for (int o = 16; o > 0; o >>= 1) v += __shfl_xor_sync(0xffffffffu, v, o);
    return v;
}
__device__ __forceinline__ u64 dup2(float x) {
    u64 r; asm("mov.b64 %0, {%1, %1};" : "=l"(r) : "f"(x)); return r;
}
__device__ __forceinline__ u64 fma2(u64 a, u64 b, u64 c) {
    u64 d; asm("fma.rn.f32x2 %0, %1, %2, %3;" : "=l"(d) : "l"(a), "l"(b), "l"(c)); return d;
}
__device__ __forceinline__ void unpack2(u64 p, float& lo, float& hi) {
    asm("mov.b64 {%0, %1}, %2;" : "=f"(lo), "=f"(hi) : "l"(p));
}

extern "C" __global__ void __launch_bounds__(NTHREADS, 1)
vq_fused_kernel(const float* __restrict__ emb,
                const float* __restrict__ W1, const float* __restrict__ b1,
                const float* __restrict__ g1, const float* __restrict__ be1,
                const float* __restrict__ W2, const float* __restrict__ b2,
                const float* __restrict__ g2, const float* __restrict__ be2,
                const float* __restrict__ cb,
                float* __restrict__ outZ,
                float* __restrict__ outIdx,
                float* __restrict__ outLoss,
                int writeAux)
{
    extern __shared__ float sm[];
    float*  sX   = sm;                        // 64x384
    float*  sH   = sm;                        // 64x256 (aliases sX after GEMM1)
    float*  sZ   = sm + 16384;                // 64x128
    float*  sW   = sm + 24576;                // tiles
    float*  sCn  = sm + 33024;                // 256
    double* sLoss = (double*)(sm + 33280);    // 8 doubles

    const int tid  = threadIdx.x;
    const int wid  = tid >> 5;
    const int lane = tid & 31;
    const int rb   = wid * 8;                 // this warp's 8 rows within the 64-row tile
    const int r0   = blockIdx.x * TM;
    const int cA0  = lane * 4;                // column group A: cols [4*lane, 4*lane+3]
    const int cB0  = 128 + lane * 4;          // column group B: cols [128+4*lane, ...]

    // ---- stage X tile (coalesced float4) ----
    {
        const float4* e4 = (const float4*)emb + (size_t)r0 * (DIN / 4);
        float4* x4 = (float4*)sX;
#pragma unroll
        for (int i = 0; i < 24; i++) x4[tid + i * 256] = e4[tid + i * 256];
    }
    // ---- codebook squared norms (one code per thread) ----
    {
        const float4* cv4 = (const float4*)cb + (size_t)tid * (DLAT / 4);
        float s = 0.f;
#pragma unroll
        for (int q = 0; q < 32; q++) {
            float4 v = cv4[q];
            s += v.x * v.x + v.y * v.y + v.z * v.z + v.w * v.w;
        }
        sCn[tid] = s;
    }

    // =================== GEMM1: [64,384] @ W1[384,256]  (f32x2, contiguous lanes) ===================
    // acc1[i][0..1] = cols (cA0, cA0+1), (cA0+2, cA0+3); acc1[i][2..3] = group B likewise.
    u64 acc1[8][4];
#pragma unroll
    for (int i = 0; i < 8; i++)
#pragma unroll
        for (int p = 0; p < 4; p++) acc1[i][p] = 0ULL;

    for (int kt = 0; kt < DIN; kt += 32) {
        __syncthreads();
        {
            const float4* w4 = (const float4*)W1 + kt * 64;
            float4* t4 = (float4*)sW;
#pragma unroll
            for (int i = 0; i < 8; i++) t4[tid + i * 256] = w4[tid + i * 256];
        }
        __syncthreads();
#pragma unroll
        for (int kg = 0; kg < 8; kg++) {
            float4 xv[8];
#pragma unroll
            for (int i = 0; i < 8; i++)
                xv[i] = *(const float4*)&sX[(rb + i) * 384 + kt + kg * 4];
#pragma unroll
            for (int kq = 0; kq < 4; kq++) {
                const int kk = kg * 4 + kq;
                ulonglong2 wA = ((const ulonglong2*)sW)[kk * 64 + lane];       // cols 4l..4l+3
                ulonglong2 wB = ((const ulonglong2*)sW)[kk * 64 + 32 + lane];  // cols 128+4l..
#pragma unroll
                for (int i = 0; i < 8; i++) {
                    float xs = (kq == 0) ? xv[i].x : (kq == 1) ? xv[i].y : (kq == 2) ? xv[i].z : xv[i].w;
                    u64 xx = dup2(xs);
                    acc1[i][0] = fma2(xx, wA.x, acc1[i][0]);
                    acc1[i][1] = fma2(xx, wA.y, acc1[i][1]);
                    acc1[i][2] = fma2(xx, wB.x, acc1[i][2]);
                    acc1[i][3] = fma2(xx, wB.y, acc1[i][3]);
                }
            }
        }
    }
    __syncthreads();   // all reads of sX/sW done before sH overwrites sX

    // =================== bias + LayerNorm1 + exact GELU ===================
    {
        float4 bA = *(const float4*)(b1 + cA0),  bB = *(const float4*)(b1 + cB0);
        float4 gA = *(const float4*)(g1 + cA0),  gB = *(const float4*)(g1 + cB0);
        float4 eA = *(const float4*)(be1 + cA0), eB = *(const float4*)(be1 + cB0);
        float b1v[8] = {bA.x,bA.y,bA.z,bA.w,bB.x,bB.y,bB.z,bB.w};
        float g1v[8] = {gA.x,gA.y,gA.z,gA.w,gB.x,gB.y,gB.z,gB.w};
        float e1v[8] = {eA.x,eA.y,eA.z,eA.w,eB.x,eB.y,eB.z,eB.w};
#pragma unroll
        for (int i = 0; i < 8; i++) {
            float v[8], s = 0.f;
#pragma unroll
            for (int p = 0; p < 4; p++) unpack2(acc1[i][p], v[2*p], v[2*p+1]);
#pragma unroll
            for (int j = 0; j < 8; j++) { v[j] = v[j] + b1v[j]; s += v[j]; }
            s = warp_sum(s);
            float mean = s * (1.f / 256.f);
            float ss = 0.f;
#pragma unroll
            for (int j = 0; j < 8; j++) { float d = v[j] - mean; ss += d * d; }
            ss = warp_sum(ss);
            float rstd = rsqrtf(ss * (1.f / 256.f) + 1e-5f);
#pragma unroll
            for (int j = 0; j < 8; j++) {
                float t = (v[j] - mean) * rstd * g1v[j] + e1v[j];
                float h = 0.5f * t * (1.f + erff(t * 0.70710678118654752f));
                int col = (j < 4) ? (cA0 + j) : (cB0 + j - 4);
                sH[(rb + i) * 256 + col] = h;
            }
        }
    }
    __syncthreads();

    // =================== GEMM2: [64,256] @ W2[256,128]  (f32x2) ===================
    u64 acc2[8][2];
#pragma unroll
    for (int i = 0; i < 8; i++) { acc2[i][0] = 0ULL; acc2[i][1] = 0ULL; }

    for (int kt = 0; kt < DHID; kt += 32) {
        __syncthreads();
        {
            const float4* w4 = (const float4*)W2 + kt * 32;
            float4* t4 = (float4*)sW;
#pragma unroll
            for (int i = 0; i < 4; i++) t4[tid + i * 256] = w4[tid + i * 256];
        }
        __syncthreads();
#pragma unroll
        for (int kg = 0; kg < 8; kg++) {
            float4 xv[8];
#pragma unroll
            for (int i = 0; i < 8; i++)
                xv[i] = *(const float4*)&sH[(rb + i) * 256 + kt + kg * 4];
#pragma unroll
            for (int kq = 0; kq < 4; kq++) {
                const int kk = kg * 4 + kq;
                ulonglong2 wv = ((const ulonglong2*)sW)[kk * 32 + lane];   // cols 4l..4l+3
#pragma unroll
                for (int i = 0; i < 8; i++) {
                    float xs = (kq == 0) ? xv[i].x : (kq == 1) ? xv[i].y : (kq == 2) ? xv[i].z : xv[i].w;
                    u64 xx = dup2(xs);
                    acc2[i][0] = fma2(xx, wv.x, acc2[i][0]);
                    acc2[i][1] = fma2(xx, wv.y, acc2[i][1]);
                }
            }
        }
    }
    __syncthreads();

    // =================== bias + LayerNorm2 -> z, ||z||^2 ===================
    float zsq[8];
    {
        float4 b2v = *(const float4*)(b2 + cA0);
        float4 g2v = *(const float4*)(g2 + cA0);
        float4 e2v = *(const float4*)(be2 + cA0);
#pragma unroll
        for (int i = 0; i < 8; i++) {
            float a0, a1, a2, a3;
            unpack2(acc2[i][0], a0, a1);
            unpack2(acc2[i][1], a2, a3);
            float v0 = a0 + b2v.x, v1 = a1 + b2v.y;
            float v2 = a2 + b2v.z, v3 = a3 + b2v.w;
            float s = warp_sum(v0 + v1 + v2 + v3);
            float mean = s * (1.f / 128.f);
            float d0 = v0 - mean, d1 = v1 - mean, d2 = v2 - mean, d3 = v3 - mean;
            float ss = warp_sum(d0 * d0 + d1 * d1 + d2 * d2 + d3 * d3);
            float rstd = rsqrtf(ss * (1.f / 128.f) + 1e-5f);
            float z0 = d0 * rstd * g2v.x + e2v.x;
            float z1 = d1 * rstd * g2v.y + e2v.y;
            float z2 = d2 * rstd * g2v.z + e2v.z;
            float z3 = d3 * rstd * g2v.w + e2v.w;
            zsq[i] = warp_sum(z0 * z0 + z1 * z1 + z2 * z2 + z3 * z3);
            float* zr = sZ + (rb + i) * 128 + cA0;
            zr[0] = z0; zr[1] = z1; zr[2] = z2; zr[3] = z3;
        }
    }
    __syncthreads();

    // =================== distance GEMM: z[64,128] . cb[256,128]^T  (f32x2) ===================
    u64 acc3[8][4];
#pragma unroll
    for (int i = 0; i < 8; i++)
#pragma unroll
        for (int p = 0; p < 4; p++) acc3[i][p] = 0ULL;

    for (int kt = 0; kt < DLAT; kt += 32) {
        __syncthreads();
        // stage transposed codebook tile: sW[kk*264 + code] = cb[code][kt+kk]
        {
            const float4* cv4 = (const float4*)cb + (size_t)tid * 32 + (kt >> 2);
#pragma unroll
            for (int q = 0; q < 8; q++) {
                float4 v = cv4[q];
                int kk = q * 4;
                sW[(kk + 0) * 264 + tid] = v.x;
                sW[(kk + 1) * 264 + tid] = v.y;
                sW[(kk + 2) * 264 + tid] = v.z;
                sW[(kk + 3) * 264 + tid] = v.w;
            }
        }
        __syncthreads();
#pragma unroll
        for (int kg = 0; kg < 8; kg++) {
            float4 zv[8];
#pragma unroll
            for (int i = 0; i < 8; i++)
                zv[i] = *(const float4*)&sZ[(rb + i) * 128 + kt + kg * 4];
#pragma unroll
            for (int kq = 0; kq < 4; kq++) {
                const int kk = kg * 4 + kq;
                ulonglong2 cA = ((const ulonglong2*)sW)[kk * 66 + lane];       // codes 4l..4l+3
                ulonglong2 cB = ((const ulonglong2*)sW)[kk * 66 + 32 + lane];  // codes 128+4l..
#pragma unroll
                for (int i = 0; i < 8; i++) {
                    float zs = (kq == 0) ? zv[i].x : (kq == 1) ? zv[i].y : (kq == 2) ? zv[i].z : zv[i].w;
                    u64 zz = dup2(zs);
                    acc3[i][0] = fma2(zz, cA.x, acc3[i][0]);
                    acc3[i][1] = fma2(zz, cA.y, acc3[i][1]);
                    acc3[i][2] = fma2(zz, cB.x, acc3[i][2]);
                    acc3[i][3] = fma2(zz, cB.y, acc3[i][3]);
                }
            }
        }
    }

    // ---- codebook norms for this thread's 8 codes ----
    float cnA[4], cnB[4];
#pragma unroll
    for (int q = 0; q < 4; q++) { cnA[q] = sCn[cA0 + q]; cnB[q] = sCn[cB0 + q]; }

    // =================== argmin + outputs + loss ===================
    double lsum = 0.0;
#pragma unroll
    for (int i = 0; i < 8; i++) {
        float dot[8];
#pragma unroll
        for (int p = 0; p < 4; p++) unpack2(acc3[i][p], dot[2*p], dot[2*p+1]);
        float best = INFINITY;
        int   bidx = 0x7fffffff;
#pragma unroll
        for (int j = 0; j < 8; j++) {
            int   idx = (j < 4) ? (cA0 + j) : (cB0 + j - 4);
            float cn  = (j < 4) ? cnA[j] : cnB[j - 4];
            // mimic reference rounding: (||z||^2 + ||c||^2) - 2*dot, fp32
            float d = (zsq[i] + cn) - 2.0f * dot[j];
            if (d < best || (d == best && idx < bidx)) { best = d; bidx = idx; }
        }
#pragma unroll
        for (int o = 16; o > 0; o >>= 1) {
            float ob = __shfl_xor_sync(0xffffffffu, best, o);
            int   oi = __shfl_xor_sync(0xffffffffu, bidx, o);
            if (ob < best || (ob == best && oi < bidx)) { best = ob; bidx = oi; }
        }
        int r = r0 + rb + i;
        if (lane == 0 && writeAux) outIdx[r] = (float)bidx;
        float4 cv = ((const float4*)cb)[bidx * 32 + lane];
        ((float4*)outZ)[(size_t)r * 32 + lane] = cv;
        float4 zv = ((float4*)sZ)[(rb + i) * 32 + lane];
        float d0 = cv.x - zv.x, d1 = cv.y - zv.y, d2 = cv.z - zv.z, d3 = cv.w - zv.w;
        lsum += (double)(d0 * d0 + d1 * d1 + d2 * d2 + d3 * d3);
    }

#pragma unroll
    for (int o = 16; o > 0; o >>= 1) lsum += __shfl_down_sync(0xffffffffu, lsum, o);
    if (lane == 0) sLoss[wid] = lsum;
    __syncthreads();

    // ---- per-block partial + last-block finalize (single-kernel loss) ----
    if (!writeAux) return;
    __shared__ unsigned int sIsLast;
    if (tid == 0) {
        double t = 0.0;
#pragma unroll
        for (int w = 0; w < 8; w++) t += sLoss[w];
        g_partials[blockIdx.x] = t;
        __threadfence();
        unsigned int old = atomicAdd(&g_ticket, 1u);
        sIsLast = (old == (unsigned int)(gridDim.x - 1)) ? 1u : 0u;
    }
    __syncthreads();
    if (sIsLast) {
        __threadfence();
        double s = 0.0;
#pragma unroll
        for (int q = 0; q < NBLOCKS / NTHREADS; q++)
            s += g_partials[tid * (NBLOCKS / NTHREADS) + q];
#pragma unroll
        for (int o = 16; o > 0; o >>= 1) s += __shfl_down_sync(0xffffffffu, s, o);
        if (lane == 0) sLoss[wid] = s;
        __syncthreads();
        if (tid == 0) {
            double t = 0.0;
#pragma unroll
            for (int w = 0; w < 8; w++) t += sLoss[w];
            outLoss[0] = (float)(1.25 * t / (double)((long long)NROWS * DLAT));
            g_ticket = 0;   // reset for next (graph-replayed) launch
        }
    }
}

extern "C" void kernel_launch(void* const* d_in, const int* in_sizes, int n_in,
                              void* d_out, int out_size)
{
    const float* emb = (const float*)d_in[0];
    const float* W1  = (const float*)d_in[1];
    const float* b1  = (const float*)d_in[2];
    const float* g1  = (const float*)d_in[3];
    const float* be1 = (const float*)d_in[4];
    const float* W2  = (const float*)d_in[5];
    const float* b2  = (const float*)d_in[6];
    const float* g2  = (const float*)d_in[7];
    const float* be2 = (const float*)d_in[8];
    const float* cb  = (const float*)d_in[9];

    float* out     = (float*)d_out;
    float* outZ    = out;
    float* outLoss = out + (size_t)NROWS * DLAT;     // after 16777216 z_q floats
    float* outIdx  = outLoss + 1;                     // then 131072 indices (as float)
    int writeAux = (out_size >= NROWS * DLAT + 1 + NROWS) ? 1 : 0;

    cudaFuncSetAttribute(vq_fused_kernel,
                         cudaFuncAttributeMaxDynamicSharedMemorySize, SMEM_BYTES);

    vq_fused_kernel<<<NBLOCKS, NTHREADS, SMEM_BYTES>>>(
        emb, W1, b1, g1, be1, W2, b2, g2, be2, cb, outZ, outIdx, outLoss, writeAux);
}